// round 5
// baseline (speedup 1.0000x reference)
#include <cuda_runtime.h>
#include <math.h>

#define BT    64
#define NPIX  49
#define CDIM  2048
#define VOCAB 10000

// ---------------- scratch ----------------
__device__ float g_s[BT*512];
__device__ float g_g2[BT*512];
__device__ float g_alpha0[BT*CDIM];              // raw cxt scores (unnormalized)
__device__ float g_Mpart[4*BT*NPIX*NPIX];
__device__ float g_cchanp[4*BT*NPIX];
__device__ float g_cspat[BT*CDIM];
__device__ float g_sgate[BT*512];
__device__ float g_cgate[BT*512];
__device__ float g_spart[4*BT*512];
__device__ float g_chat[BT*512];

__device__ __forceinline__ float tanh_fast(float x) {
    float y;
    asm("tanh.approx.f32 %0, %1;" : "=f"(y) : "f"(x));
    return y;
}
__device__ __forceinline__ float sigmoidf_(float x) {
    return 1.0f / (1.0f + __expf(-x));
}

// ---------------------------------------------------------------------------
// z=0: s = sigmoid(x@Wsx + hprev@Wsh)*tanh(cells);  z=1: g2 = h@Wg2
// ---------------------------------------------------------------------------
__global__ void pre_kernel(const float* __restrict__ x,
                           const float* __restrict__ hiddens,
                           const float* __restrict__ cells,
                           const float* __restrict__ Wsx,
                           const float* __restrict__ Wsh,
                           const float* __restrict__ Wg2) {
    __shared__ __align__(16) float As[16][64];
    const int op = blockIdx.z;
    const int n0 = blockIdx.x * 32, m0 = blockIdx.y * 16;
    const int col = n0 + (threadIdx.x & 31);
    const int rl  = (threadIdx.x >> 5) * 2;
    const int r0  = m0 + rl;
    float acc0 = 0.f, acc1 = 0.f;
    const int nph = (op == 0) ? 2 : 1;
    for (int phase = 0; phase < nph; ++phase) {
        const float* W = (op == 0) ? (phase ? Wsh : Wsx) : Wg2;
        for (int k0 = 0; k0 < 512; k0 += 64) {
            __syncthreads();
            for (int i = threadIdx.x; i < 1024; i += 256) {
                int r = m0 + (i >> 6), kk = i & 63;
                float v;
                if (op == 0 && phase == 1) v = (r & 7) ? hiddens[(r - 1) * 512 + k0 + kk] : 0.f;
                else if (op == 0)          v = x[r * 512 + k0 + kk];
                else                       v = hiddens[r * 512 + k0 + kk];
                As[i >> 6][kk] = v;
            }
            __syncthreads();
            #pragma unroll 8
            for (int kk = 0; kk < 64; kk++) {
                float w = W[(k0 + kk) * 512 + col];
                acc0 += As[rl][kk]     * w;
                acc1 += As[rl + 1][kk] * w;
            }
        }
    }
    if (op == 0) {
        g_s[r0 * 512 + col]       = sigmoidf_(acc0) * tanh_fast(cells[r0 * 512 + col]);
        g_s[(r0 + 1) * 512 + col] = sigmoidf_(acc1) * tanh_fast(cells[(r0 + 1) * 512 + col]);
    } else {
        g_g2[r0 * 512 + col]       = acc0;
        g_g2[(r0 + 1) * 512 + col] = acc1;
    }
}

// ---------------------------------------------------------------------------
// cxt with fused featmean. grid (64 bt, 4 chunks of 512), 128 thr x 4 d.
// ---------------------------------------------------------------------------
__global__ void cxt_kernel(const float* __restrict__ V,
                           const float* __restrict__ Wfeat,
                           const float* __restrict__ Wcxt) {
    __shared__ __align__(16) float wf[512];
    __shared__ __align__(16) float wc[512];
    __shared__ __align__(16) float gr[512];
    const int bt = blockIdx.x, b = bt >> 3;
    const int t = threadIdx.x;
    for (int i = t; i < 512; i += 128) {
        wf[i] = Wfeat[i];
        wc[i] = Wcxt[i];
        gr[i] = g_g2[bt * 512 + i];
    }
    const int d0 = blockIdx.y * 512 + t;
    // featmean for this thread's 4 d's
    float a[4];
    #pragma unroll
    for (int q = 0; q < 4; q++) {
        int d = d0 + 128 * q;
        float s = 0.f;
        #pragma unroll 7
        for (int k = 0; k < NPIX; k++) s += V[(b * NPIX + k) * CDIM + d];
        a[q] = s * (1.0f / 49.0f);
    }
    __syncthreads();
    float c0 = 0.f, c1 = 0.f, c2 = 0.f, c3 = 0.f;
    #pragma unroll 4
    for (int j = 0; j < 512; j++) {
        float wfj = wf[j], grj = gr[j], wcj = wc[j];
        c0 += tanh_fast(fmaf(a[0], wfj, grj)) * wcj;
        c1 += tanh_fast(fmaf(a[1], wfj, grj)) * wcj;
        c2 += tanh_fast(fmaf(a[2], wfj, grj)) * wcj;
        c3 += tanh_fast(fmaf(a[3], wfj, grj)) * wcj;
    }
    g_alpha0[bt * CDIM + d0]       = c0;
    g_alpha0[bt * CDIM + d0 + 128] = c1;
    g_alpha0[bt * CDIM + d0 + 256] = c2;
    g_alpha0[bt * CDIM + d0 + 384] = c3;
}

// ---------------------------------------------------------------------------
// wfwv with fused softmax + cchan. grid (64 bt, 4 dp), 128 thr.
// compute: M[k][k2] partials via 13x7 threads x (4 rows x 8 cols) tiles.
// threads 96..127 accumulate cchan row sums.
// ---------------------------------------------------------------------------
__global__ void wfwv_kernel(const float* __restrict__ V,
                            const float* __restrict__ Wv) {
    __shared__ __align__(16) float aVT[64][52];   // [dd][row], rows padded to 52
    __shared__ __align__(16) float Wvs[64][56];   // [dd][col], cols padded to 56
    __shared__ __align__(16) float alp[512];
    __shared__ float red[128];
    const int bt = blockIdx.x, b = bt >> 3;
    const int dp = blockIdx.y, d0 = dp * 512;
    const int t = threadIdx.x;
    const float* arow = g_alpha0 + bt * CDIM;

    // block-wide softmax stats over the full 2048 row (redundant across dp; L2 hits)
    float mx = -1e30f;
    for (int i = t; i < CDIM; i += 128) mx = fmaxf(mx, arow[i]);
    red[t] = mx; __syncthreads();
    for (int s = 64; s > 0; s >>= 1) { if (t < s) red[t] = fmaxf(red[t], red[t + s]); __syncthreads(); }
    mx = red[0]; __syncthreads();
    float sm = 0.f;
    for (int i = t; i < CDIM; i += 128) sm += __expf(arow[i] - mx);
    red[t] = sm; __syncthreads();
    for (int s = 64; s > 0; s >>= 1) { if (t < s) red[t] += red[t + s]; __syncthreads(); }
    const float inv = 1.0f / red[0];
    for (int i = t; i < 512; i += 128) alp[i] = __expf(arow[d0 + i] - mx) * inv;
    // zero-pad Wvs cols 49..55
    for (int i = t; i < 64 * 7; i += 128) Wvs[i / 7][49 + (i % 7)] = 0.f;

    const int tr = t / 7, tc = t % 7;       // t<91: tile (4 rows x 8 cols)
    const bool active = (t < 91);
    float acc[4][8];
    #pragma unroll
    for (int i = 0; i < 4; i++)
        #pragma unroll
        for (int j = 0; j < 8; j++) acc[i][j] = 0.f;
    const int crow = t - 96;                 // threads 96..127 -> rows crow, crow+32
    float chs0 = 0.f, chs1 = 0.f;

    for (int c = 0; c < 8; c++) {
        __syncthreads();
        for (int i = t; i < 49 * 64; i += 128) {
            int r = i >> 6, dd = i & 63;
            aVT[dd][r] = V[(b * NPIX + r) * CDIM + d0 + c * 64 + dd] * alp[c * 64 + dd];
        }
        for (int i = t; i < 64 * 49; i += 128) {
            int dd = i / 49, k2 = i % 49;
            Wvs[dd][k2] = Wv[(size_t)(d0 + c * 64 + dd) * NPIX + k2];
        }
        __syncthreads();
        if (active) {
            #pragma unroll 4
            for (int dd = 0; dd < 64; dd++) {
                const float4 av = *reinterpret_cast<const float4*>(&aVT[dd][tr * 4]);
                const float4 w0 = *reinterpret_cast<const float4*>(&Wvs[dd][tc * 8]);
                const float4 w1 = *reinterpret_cast<const float4*>(&Wvs[dd][tc * 8 + 4]);
                acc[0][0] += av.x * w0.x; acc[0][1] += av.x * w0.y; acc[0][2] += av.x * w0.z; acc[0][3] += av.x * w0.w;
                acc[0][4] += av.x * w1.x; acc[0][5] += av.x * w1.y; acc[0][6] += av.x * w1.z; acc[0][7] += av.x * w1.w;
                acc[1][0] += av.y * w0.x; acc[1][1] += av.y * w0.y; acc[1][2] += av.y * w0.z; acc[1][3] += av.y * w0.w;
                acc[1][4] += av.y * w1.x; acc[1][5] += av.y * w1.y; acc[1][6] += av.y * w1.z; acc[1][7] += av.y * w1.w;
                acc[2][0] += av.z * w0.x; acc[2][1] += av.z * w0.y; acc[2][2] += av.z * w0.z; acc[2][3] += av.z * w0.w;
                acc[2][4] += av.z * w1.x; acc[2][5] += av.z * w1.y; acc[2][6] += av.z * w1.z; acc[2][7] += av.z * w1.w;
                acc[3][0] += av.w * w0.x; acc[3][1] += av.w * w0.y; acc[3][2] += av.w * w0.z; acc[3][3] += av.w * w0.w;
                acc[3][4] += av.w * w1.x; acc[3][5] += av.w * w1.y; acc[3][6] += av.w * w1.z; acc[3][7] += av.w * w1.w;
            }
        } else if (t >= 96) {
            float s0 = 0.f, s1 = 0.f;
            #pragma unroll 8
            for (int dd = 0; dd < 64; dd++) {
                s0 += aVT[dd][crow];
                if (crow + 32 < NPIX) s1 += aVT[dd][crow + 32];
            }
            chs0 += s0; chs1 += s1;
        }
    }
    if (active) {
        #pragma unroll
        for (int i = 0; i < 4; i++) {
            int k = tr * 4 + i;
            if (k >= NPIX) continue;
            #pragma unroll
            for (int j = 0; j < 8; j++) {
                int k2 = tc * 8 + j;
                if (k2 < NPIX)
                    g_Mpart[(((size_t)dp * BT + bt) * NPIX + k) * NPIX + k2] = acc[i][j];
            }
        }
    } else if (t >= 96) {
        g_cchanp[(dp * BT + bt) * NPIX + crow] = chs0;
        if (crow + 32 < NPIX) g_cchanp[(dp * BT + bt) * NPIX + crow + 32] = chs1;
    }
}

// ---------------------------------------------------------------------------
// zt: fused gcs + z_t + softmaxes + c_spatial. grid 64 x 256 thr.
// ---------------------------------------------------------------------------
__global__ void zt_kernel(const float* __restrict__ hiddens,
                          const float* __restrict__ V,
                          const float* __restrict__ Wg,
                          const float* __restrict__ Ws,
                          const float* __restrict__ Wh,
                          float* __restrict__ out_alpha,
                          float* __restrict__ out_beta) {
    __shared__ float h_sm[512], s_sm[512];
    __shared__ float Msum[NPIX * NPIX];
    __shared__ float pg[8][NPIX], ps[8][NPIX];
    __shared__ float gg[NPIX], css[NPIX], wh[NPIX], ztv[NPIX], al[NPIX];
    const int bt = blockIdx.x, b = bt >> 3, t = threadIdx.x;
    for (int i = t; i < 512; i += 256) {
        h_sm[i] = hiddens[bt * 512 + i];
        s_sm[i] = g_s[bt * 512 + i];
    }
    if (t < NPIX) wh[t] = Wh[t];
    {
        const float* p0 = g_Mpart + (size_t)bt * NPIX * NPIX;
        const float* p1 = p0 + (size_t)BT * NPIX * NPIX;
        const float* p2 = p1 + (size_t)BT * NPIX * NPIX;
        const float* p3 = p2 + (size_t)BT * NPIX * NPIX;
        for (int i = t; i < NPIX * NPIX; i += 256)
            Msum[i] = p0[i] + p1[i] + p2[i] + p3[i];
    }
    __syncthreads();
    // gcs: warp w covers k in [w*64, w*64+64); lanes cover outputs j, j+32.
    {
        const int w = t >> 5, lane = t & 31;
        float gp0 = 0.f, sp0 = 0.f, gp1 = 0.f, sp1 = 0.f;
        const int j1 = lane + 32;
        for (int kk = 0; kk < 64; kk++) {
            int k = w * 64 + kk;
            float hk = h_sm[k], sk = s_sm[k];
            gp0 += hk * Wg[k * NPIX + lane];
            sp0 += sk * Ws[k * NPIX + lane];
            if (j1 < NPIX) {
                gp1 += hk * Wg[k * NPIX + j1];
                sp1 += sk * Ws[k * NPIX + j1];
            }
        }
        pg[w][lane] = gp0; ps[w][lane] = sp0;
        if (j1 < NPIX) { pg[w][j1] = gp1; ps[w][j1] = sp1; }
    }
    __syncthreads();
    if (t < NPIX) {
        float gv = 0.f, sv = 0.f;
        #pragma unroll
        for (int w = 0; w < 8; w++) { gv += pg[w][t]; sv += ps[w][t]; }
        gg[t] = gv;
        css[t] = sv + gv;
    }
    __syncthreads();
    if (t < NPIX) {
        float z = 0.f;
        #pragma unroll 7
        for (int k2 = 0; k2 < NPIX; k2++)
            z += tanh_fast(tanh_fast(Msum[t * NPIX + k2] + gg[k2])) * wh[k2];
        ztv[t] = z;
    }
    __syncthreads();
    if (t == 0) {
        float ze = 0.f;
        for (int k = 0; k < NPIX; k++) ze += tanh_fast(css[k]) * wh[k];
        float mx = -1e30f;
        for (int k = 0; k < NPIX; k++) mx = fmaxf(mx, ztv[k]);
        float sm = 0.f;
        for (int k = 0; k < NPIX; k++) sm += __expf(ztv[k] - mx);
        float inv = 1.0f / sm;
        for (int k = 0; k < NPIX; k++) {
            float a = __expf(ztv[k] - mx) * inv;
            al[k] = a;
            out_alpha[bt * NPIX + k] = a;
        }
        float mx2 = fmaxf(mx, ze);
        float sm2 = 0.f;
        for (int k = 0; k < NPIX; k++) sm2 += __expf(ztv[k] - mx2);
        sm2 += __expf(ze - mx2);
        out_beta[bt] = __expf(ze - mx2) / sm2;
    }
    __syncthreads();
    // c_spatial: all 256 threads over d
    for (int d = t; d < CDIM; d += 256) {
        float s = 0.f;
        #pragma unroll 7
        for (int k = 0; k < NPIX; k++) s += al[k] * V[(b * NPIX + k) * CDIM + d];
        g_cspat[bt * CDIM + d] = s;
    }
}

// ---------------------------------------------------------------------------
// gates: z=0 -> sgate, z=1 -> cgate. grid (16,4,2), 256 thr.
// ---------------------------------------------------------------------------
__global__ void gates_kernel(const float* __restrict__ hiddens,
                             const float* __restrict__ Wgvs,
                             const float* __restrict__ Wghs,
                             const float* __restrict__ Wgvc,
                             const float* __restrict__ Wghc) {
    __shared__ __align__(16) float As[16][64];
    const int op = blockIdx.z;
    const int n0 = blockIdx.x * 32, m0 = blockIdx.y * 16;
    const int col = n0 + (threadIdx.x & 31);
    const int rl  = (threadIdx.x >> 5) * 2;
    const int r0  = m0 + rl;
    float acc0 = 0.f, acc1 = 0.f;
    for (int phase = 0; phase < 2; ++phase) {
        const float* A = phase ? hiddens : g_s;
        const float* W = phase ? (op ? Wghc : Wghs) : (op ? Wgvc : Wgvs);
        for (int k0 = 0; k0 < 512; k0 += 64) {
            __syncthreads();
            for (int i = threadIdx.x; i < 1024; i += 256) {
                int r = m0 + (i >> 6), kk = i & 63;
                As[i >> 6][kk] = A[r * 512 + k0 + kk];
            }
            __syncthreads();
            #pragma unroll 8
            for (int kk = 0; kk < 64; kk++) {
                float w = W[(k0 + kk) * 512 + col];
                acc0 += As[rl][kk]     * w;
                acc1 += As[rl + 1][kk] * w;
            }
        }
    }
    float* out = op ? g_cgate : g_sgate;
    out[r0 * 512 + col]       = sigmoidf_(acc0);
    out[(r0 + 1) * 512 + col] = sigmoidf_(acc1);
}

// ---------------------------------------------------------------------------
// spat partial: grid (16,4,4), 256 thr
// ---------------------------------------------------------------------------
__global__ void spatpart_kernel(const float* __restrict__ Wspat) {
    __shared__ __align__(16) float As[16][64];
    const int zc = blockIdx.z, kb = zc * 512;
    const int n0 = blockIdx.x * 32, m0 = blockIdx.y * 16;
    const int col = n0 + (threadIdx.x & 31);
    const int rl  = (threadIdx.x >> 5) * 2;
    const int r0  = m0 + rl;
    float acc0 = 0.f, acc1 = 0.f;
    for (int k0 = 0; k0 < 512; k0 += 64) {
        __syncthreads();
        for (int i = threadIdx.x; i < 1024; i += 256) {
            int r = m0 + (i >> 6), kk = i & 63;
            As[i >> 6][kk] = g_cspat[r * CDIM + kb + k0 + kk];
        }
        __syncthreads();
        #pragma unroll 8
        for (int kk = 0; kk < 64; kk++) {
            float w = Wspat[(size_t)(kb + k0 + kk) * 512 + col];
            acc0 += As[rl][kk]     * w;
            acc1 += As[rl + 1][kk] * w;
        }
    }
    g_spart[(zc * BT + r0) * 512 + col]       = acc0;
    g_spart[(zc * BT + r0 + 1) * 512 + col]   = acc1;
}

// ---------------------------------------------------------------------------
// combine: g_chat = sgate*spat + cgate*(cchan@Wchan) + h.  64 x 512.
// ---------------------------------------------------------------------------
__global__ void combine_kernel(const float* __restrict__ hiddens,
                               const float* __restrict__ Wchan) {
    __shared__ float ch[NPIX];
    const int r = blockIdx.x, c = threadIdx.x;
    if (c < NPIX) {
        float v = g_cchanp[r * NPIX + c]
                + g_cchanp[(BT + r) * NPIX + c]
                + g_cchanp[(2 * BT + r) * NPIX + c]
                + g_cchanp[(3 * BT + r) * NPIX + c];
        ch[c] = v * (1.0f / 2048.0f);
    }
    __syncthreads();
    float spat = g_spart[r * 512 + c]
               + g_spart[(BT + r) * 512 + c]
               + g_spart[(2 * BT + r) * 512 + c]
               + g_spart[(3 * BT + r) * 512 + c];
    float cb = 0.f;
    #pragma unroll 7
    for (int k = 0; k < NPIX; k++) cb += ch[k] * Wchan[k * 512 + c];
    g_chat[r * 512 + c] = g_sgate[r * 512 + c] * spat
                        + g_cgate[r * 512 + c] * cb
                        + hiddens[r * 512 + c];
}

// ---------------------------------------------------------------------------
// scores = chat @ Wmlp + bmlp.  grid 157, 128 thr, tile 64x64,
// thread = 8 rows x 4 cols (float4 weight loads).
// ---------------------------------------------------------------------------
__global__ void scores_kernel(const float* __restrict__ Wmlp,
                              const float* __restrict__ bmlp,
                              float* __restrict__ out) {
    __shared__ __align__(16) float As[64][33];
    const int n0 = blockIdx.x * 64;
    const int rowg = threadIdx.x >> 4;       // 0..7 -> rows rowg*8..+7
    const int colg = threadIdx.x & 15;       // 0..15 -> cols n0+colg*4
    const int c0 = n0 + colg * 4;
    const bool okfull = (c0 + 3 < VOCAB);
    float acc[8][4];
    #pragma unroll
    for (int r = 0; r < 8; r++)
        #pragma unroll
        for (int j = 0; j < 4; j++) acc[r][j] = 0.f;
    for (int k0 = 0; k0 < 512; k0 += 32) {
        __syncthreads();
        for (int i = threadIdx.x; i < 2048; i += 128) {
            int r = i >> 5, kk = i & 31;
            As[r][kk] = g_chat[r * 512 + k0 + kk];
        }
        __syncthreads();
        #pragma unroll 4
        for (int kk = 0; kk < 32; kk++) {
            float4 w;
            if (okfull) {
                w = *reinterpret_cast<const float4*>(&Wmlp[(size_t)(k0 + kk) * VOCAB + c0]);
            } else {
                w.x = (c0     < VOCAB) ? Wmlp[(size_t)(k0 + kk) * VOCAB + c0]     : 0.f;
                w.y = (c0 + 1 < VOCAB) ? Wmlp[(size_t)(k0 + kk) * VOCAB + c0 + 1] : 0.f;
                w.z = (c0 + 2 < VOCAB) ? Wmlp[(size_t)(k0 + kk) * VOCAB + c0 + 2] : 0.f;
                w.w = (c0 + 3 < VOCAB) ? Wmlp[(size_t)(k0 + kk) * VOCAB + c0 + 3] : 0.f;
            }
            #pragma unroll
            for (int r = 0; r < 8; r++) {
                float a = As[rowg * 8 + r][kk];
                acc[r][0] += a * w.x;
                acc[r][1] += a * w.y;
                acc[r][2] += a * w.z;
                acc[r][3] += a * w.w;
            }
        }
    }
    #pragma unroll
    for (int j = 0; j < 4; j++) {
        int c = c0 + j;
        if (c < VOCAB) {
            float bb = bmlp[c];
            #pragma unroll
            for (int r = 0; r < 8; r++)
                out[(size_t)(rowg * 8 + r) * VOCAB + c] = acc[r][j] + bb;
        }
    }
}

// ---------------------------------------------------------------------------
extern "C" void kernel_launch(void* const* d_in, const int* in_sizes, int n_in,
                              void* d_out, int out_size) {
    (void)in_sizes; (void)n_in; (void)out_size;
    const float* x       = (const float*)d_in[0];
    const float* hiddens = (const float*)d_in[1];
    const float* cells   = (const float*)d_in[2];
    const float* V       = (const float*)d_in[3];
    const float* Wsx     = (const float*)d_in[4];
    const float* Wsh     = (const float*)d_in[5];
    const float* Wv      = (const float*)d_in[6];
    const float* Wg      = (const float*)d_in[7];
    const float* Ws      = (const float*)d_in[8];
    const float* Wh      = (const float*)d_in[9];
    const float* Wfeat   = (const float*)d_in[10];
    const float* Wcxt    = (const float*)d_in[11];
    const float* Wg2     = (const float*)d_in[12];
    const float* Wspat   = (const float*)d_in[13];
    const float* Wchan   = (const float*)d_in[14];
    const float* Wgvs    = (const float*)d_in[15];
    const float* Wgvc    = (const float*)d_in[16];
    const float* Wghs    = (const float*)d_in[17];
    const float* Wghc    = (const float*)d_in[18];
    const float* Wmlp    = (const float*)d_in[19];
    const float* bmlp    = (const float*)d_in[20];

    float* out        = (float*)d_out;
    float* out_scores = out;
    float* out_alpha  = out + BT * VOCAB;
    float* out_beta   = out + BT * VOCAB + BT * NPIX;

    pre_kernel<<<dim3(16, 4, 2), 256>>>(x, hiddens, cells, Wsx, Wsh, Wg2);
    cxt_kernel<<<dim3(64, 4), 128>>>(V, Wfeat, Wcxt);
    gates_kernel<<<dim3(16, 4, 2), 256>>>(hiddens, Wgvs, Wghs, Wgvc, Wghc);
    wfwv_kernel<<<dim3(64, 4), 128>>>(V, Wv);
    zt_kernel<<<64, 256>>>(hiddens, V, Wg, Ws, Wh, out_alpha, out_beta);
    spatpart_kernel<<<dim3(16, 4, 4), 256>>>(Wspat);
    combine_kernel<<<64, 512>>>(hiddens, Wchan);
    scores_kernel<<<157, 128>>>(Wmlp, bmlp, out_scores);
}

// round 7
// speedup vs baseline: 1.0629x; 1.0629x over previous
#include <cuda_runtime.h>
#include <math.h>

#define BT    64
#define NPIX  49
#define CDIM  2048
#define VOCAB 10000
#define DSPLIT 8

// ---------------- scratch ----------------
__device__ float g_s[BT*512];
__device__ float g_g2[BT*512];
__device__ float g_alpha0[BT*CDIM];
__device__ float g_Mpart[DSPLIT*BT*NPIX*NPIX];
__device__ float g_cchanp[DSPLIT*BT*NPIX];
__device__ float g_alpha_t[BT*NPIX];
__device__ float g_cspat[BT*CDIM];
__device__ float g_sgate[BT*512];
__device__ float g_cgate[BT*512];
__device__ float g_spart[4*BT*512];
__device__ float g_chat[BT*512];

__device__ __forceinline__ float tanh_fast(float x) {
    float y;
    asm("tanh.approx.f32 %0, %1;" : "=f"(y) : "f"(x));
    return y;
}
__device__ __forceinline__ float sigmoidf_(float x) {
    return 1.0f / (1.0f + __expf(-x));
}

// ---------------------------------------------------------------------------
// z=0: s = sigmoid(x@Wsx + hprev@Wsh)*tanh(cells);  z=1: g2 = h@Wg2
// ---------------------------------------------------------------------------
__global__ void pre_kernel(const float* __restrict__ x,
                           const float* __restrict__ hiddens,
                           const float* __restrict__ cells,
                           const float* __restrict__ Wsx,
                           const float* __restrict__ Wsh,
                           const float* __restrict__ Wg2) {
    __shared__ __align__(16) float As[16][64];
    const int op = blockIdx.z;
    const int n0 = blockIdx.x * 32, m0 = blockIdx.y * 16;
    const int col = n0 + (threadIdx.x & 31);
    const int rl  = (threadIdx.x >> 5) * 2;
    const int r0  = m0 + rl;
    float acc0 = 0.f, acc1 = 0.f;
    const int nph = (op == 0) ? 2 : 1;
    for (int phase = 0; phase < nph; ++phase) {
        const float* W = (op == 0) ? (phase ? Wsh : Wsx) : Wg2;
        for (int k0 = 0; k0 < 512; k0 += 64) {
            __syncthreads();
            for (int i = threadIdx.x; i < 1024; i += 256) {
                int r = m0 + (i >> 6), kk = i & 63;
                float v;
                if (op == 0 && phase == 1) v = (r & 7) ? hiddens[(r - 1) * 512 + k0 + kk] : 0.f;
                else if (op == 0)          v = x[r * 512 + k0 + kk];
                else                       v = hiddens[r * 512 + k0 + kk];
                As[i >> 6][kk] = v;
            }
            __syncthreads();
            #pragma unroll 8
            for (int kk = 0; kk < 64; kk++) {
                float w = W[(k0 + kk) * 512 + col];
                acc0 += As[rl][kk]     * w;
                acc1 += As[rl + 1][kk] * w;
            }
        }
    }
    if (op == 0) {
        g_s[r0 * 512 + col]       = sigmoidf_(acc0) * tanhf(cells[r0 * 512 + col]);
        g_s[(r0 + 1) * 512 + col] = sigmoidf_(acc1) * tanhf(cells[(r0 + 1) * 512 + col]);
    } else {
        g_g2[r0 * 512 + col]       = acc0;
        g_g2[(r0 + 1) * 512 + col] = acc1;
    }
}

// ---------------------------------------------------------------------------
// cxt with fused featmean. grid (64 bt, 4 chunks of 512), 128 thr x 4 d.
// ---------------------------------------------------------------------------
__global__ void cxt_kernel(const float* __restrict__ V,
                           const float* __restrict__ Wfeat,
                           const float* __restrict__ Wcxt) {
    __shared__ __align__(16) float wf[512];
    __shared__ __align__(16) float wc[512];
    __shared__ __align__(16) float gr[512];
    const int bt = blockIdx.x, b = bt >> 3;
    const int t = threadIdx.x;
    for (int i = t; i < 512; i += 128) {
        wf[i] = Wfeat[i];
        wc[i] = Wcxt[i];
        gr[i] = g_g2[bt * 512 + i];
    }
    const int d0 = blockIdx.y * 512 + t;
    float a[4];
    #pragma unroll
    for (int q = 0; q < 4; q++) {
        int d = d0 + 128 * q;
        float s = 0.f;
        #pragma unroll 7
        for (int k = 0; k < NPIX; k++) s += V[(b * NPIX + k) * CDIM + d];
        a[q] = s * (1.0f / 49.0f);
    }
    __syncthreads();
    float c0 = 0.f, c1 = 0.f, c2 = 0.f, c3 = 0.f;
    #pragma unroll 4
    for (int j = 0; j < 512; j++) {
        float wfj = wf[j], grj = gr[j], wcj = wc[j];
        c0 += tanh_fast(fmaf(a[0], wfj, grj)) * wcj;
        c1 += tanh_fast(fmaf(a[1], wfj, grj)) * wcj;
        c2 += tanh_fast(fmaf(a[2], wfj, grj)) * wcj;
        c3 += tanh_fast(fmaf(a[3], wfj, grj)) * wcj;
    }
    g_alpha0[bt * CDIM + d0]       = c0;
    g_alpha0[bt * CDIM + d0 + 128] = c1;
    g_alpha0[bt * CDIM + d0 + 256] = c2;
    g_alpha0[bt * CDIM + d0 + 384] = c3;
}

// ---------------------------------------------------------------------------
// softmax over 2048 per bt (in place)
// ---------------------------------------------------------------------------
__global__ void softmax2048_kernel() {
    __shared__ float red[256];
    const int bt = blockIdx.x, t = threadIdx.x;
    float* p = g_alpha0 + bt * CDIM;
    float mx = -1e30f;
    for (int i = t; i < CDIM; i += 256) mx = fmaxf(mx, p[i]);
    red[t] = mx; __syncthreads();
    for (int s = 128; s > 0; s >>= 1) { if (t < s) red[t] = fmaxf(red[t], red[t + s]); __syncthreads(); }
    mx = red[0]; __syncthreads();
    float sm = 0.f;
    for (int i = t; i < CDIM; i += 256) { float e = __expf(p[i] - mx); p[i] = e; sm += e; }
    red[t] = sm; __syncthreads();
    for (int s = 128; s > 0; s >>= 1) { if (t < s) red[t] += red[t + s]; __syncthreads(); }
    float inv = 1.0f / red[0];
    for (int i = t; i < CDIM; i += 256) p[i] *= inv;
}

// ---------------------------------------------------------------------------
// wfwv: M partials + cchan partials. grid (64 bt, 8 dp), 192 thr, K=256/blk.
// 13x13 active threads, 4x4 register tiles; threads 169..191 do cchan rows.
// ---------------------------------------------------------------------------
__global__ void wfwv_kernel(const float* __restrict__ V,
                            const float* __restrict__ Wv) {
    __shared__ __align__(16) float Wvs[64][52];   // 52-float rows: 16B-aligned
    __shared__ __align__(16) float aV[49][65];
    __shared__ __align__(16) float as_[256];
    const int bt = blockIdx.x, b = bt >> 3;
    const int dp = blockIdx.y, d0 = dp * 256;
    const int t = threadIdx.x;
    for (int i = t; i < 256; i += 192) as_[i] = g_alpha0[bt * CDIM + d0 + i];
    if (t < 64) { Wvs[t][49] = 0.f; Wvs[t][50] = 0.f; Wvs[t][51] = 0.f; }
    const int tk = t / 13, tk2 = t % 13;
    const bool active = (t < 169);
    int ki[4];
    #pragma unroll
    for (int i = 0; i < 4; i++) ki[i] = min(tk * 4 + i, 48);
    float acc[4][4];
    #pragma unroll
    for (int i = 0; i < 4; i++)
        #pragma unroll
        for (int j = 0; j < 4; j++) acc[i][j] = 0.f;
    float chs0 = 0.f, chs1 = 0.f, chs2 = 0.f;
    const int crow = t - 169;  // 0..22
    for (int c = 0; c < 4; c++) {
        __syncthreads();
        for (int i = t; i < 49 * 64; i += 192) {
            int r = i >> 6, dd = i & 63;
            aV[r][dd] = V[(b * NPIX + r) * CDIM + d0 + c * 64 + dd] * as_[c * 64 + dd];
        }
        for (int i = t; i < 64 * 49; i += 192) {
            Wvs[i / 49][i % 49] = Wv[(size_t)(d0 + c * 64) * NPIX + i];
        }
        __syncthreads();
        if (active) {
            #pragma unroll 4
            for (int dd = 0; dd < 64; dd++) {
                const float4 wv = *reinterpret_cast<const float4*>(&Wvs[dd][tk2 * 4]);
                float av0 = aV[ki[0]][dd], av1 = aV[ki[1]][dd];
                float av2 = aV[ki[2]][dd], av3 = aV[ki[3]][dd];
                acc[0][0] += av0 * wv.x; acc[0][1] += av0 * wv.y; acc[0][2] += av0 * wv.z; acc[0][3] += av0 * wv.w;
                acc[1][0] += av1 * wv.x; acc[1][1] += av1 * wv.y; acc[1][2] += av1 * wv.z; acc[1][3] += av1 * wv.w;
                acc[2][0] += av2 * wv.x; acc[2][1] += av2 * wv.y; acc[2][2] += av2 * wv.z; acc[2][3] += av2 * wv.w;
                acc[3][0] += av3 * wv.x; acc[3][1] += av3 * wv.y; acc[3][2] += av3 * wv.z; acc[3][3] += av3 * wv.w;
            }
        } else {
            float s0 = 0.f, s1 = 0.f, s2 = 0.f;
            #pragma unroll 8
            for (int dd = 0; dd < 64; dd++) {
                s0 += aV[crow][dd];
                if (crow + 23 < 49) s1 += aV[crow + 23][dd];
                if (crow + 46 < 49) s2 += aV[crow + 46][dd];
            }
            chs0 += s0; chs1 += s1; chs2 += s2;
        }
    }
    if (active) {
        #pragma unroll
        for (int i = 0; i < 4; i++) {
            int k = tk * 4 + i;
            if (k >= NPIX) continue;
            #pragma unroll
            for (int j = 0; j < 4; j++) {
                int k2 = tk2 * 4 + j;
                if (k2 < NPIX)
                    g_Mpart[(((size_t)dp * BT + bt) * NPIX + k) * NPIX + k2] = acc[i][j];
            }
        }
    } else {
        g_cchanp[(dp * BT + bt) * NPIX + crow] = chs0;
        if (crow + 23 < 49) g_cchanp[(dp * BT + bt) * NPIX + crow + 23] = chs1;
        if (crow + 46 < 49) g_cchanp[(dp * BT + bt) * NPIX + crow + 46] = chs2;
    }
}

// ---------------------------------------------------------------------------
// zt: fused gcs + z_t + softmaxes. grid 64 blocks x 64 thr.
// ---------------------------------------------------------------------------
__global__ void zt_kernel(const float* __restrict__ hiddens,
                          const float* __restrict__ Wg,
                          const float* __restrict__ Ws,
                          const float* __restrict__ Wh,
                          float* __restrict__ out_alpha,
                          float* __restrict__ out_beta) {
    __shared__ float h_sm[512], s_sm[512];
    __shared__ float Msum[NPIX * NPIX];
    __shared__ float gg[NPIX], css[NPIX], wh[NPIX], ztv[NPIX];
    const int bt = blockIdx.x, t = threadIdx.x;
    for (int i = t; i < 512; i += 64) {
        h_sm[i] = hiddens[bt * 512 + i];
        s_sm[i] = g_s[bt * 512 + i];
    }
    if (t < NPIX) wh[t] = Wh[t];
    {
        const float* p0 = g_Mpart + (size_t)bt * NPIX * NPIX;
        const size_t stride = (size_t)BT * NPIX * NPIX;
        for (int i = t; i < NPIX * NPIX; i += 64) {
            float v = 0.f;
            #pragma unroll
            for (int p = 0; p < DSPLIT; p++) v += p0[p * stride + i];
            Msum[i] = v;
        }
    }
    __syncthreads();
    if (t < NPIX) {
        float ggv = 0.f, ssv = 0.f;
        #pragma unroll 8
        for (int k = 0; k < 512; k++) {
            ggv += h_sm[k] * Wg[k * NPIX + t];
            ssv += s_sm[k] * Ws[k * NPIX + t];
        }
        gg[t] = ggv;
        css[t] = ssv + ggv;
    }
    __syncthreads();
    if (t < NPIX) {
        float z = 0.f;
        #pragma unroll 7
        for (int k2 = 0; k2 < NPIX; k2++)
            z += tanh_fast(tanh_fast(Msum[t * NPIX + k2] + gg[k2])) * wh[k2];
        ztv[t] = z;
    }
    __syncthreads();
    if (t == 0) {
        float ze = 0.f;
        for (int k = 0; k < NPIX; k++) ze += tanh_fast(css[k]) * wh[k];
        float mx = -1e30f;
        for (int k = 0; k < NPIX; k++) mx = fmaxf(mx, ztv[k]);
        float sm = 0.f;
        for (int k = 0; k < NPIX; k++) sm += __expf(ztv[k] - mx);
        float inv = 1.0f / sm;
        for (int k = 0; k < NPIX; k++) {
            float a = __expf(ztv[k] - mx) * inv;
            g_alpha_t[bt * NPIX + k] = a;
            out_alpha[bt * NPIX + k] = a;
        }
        float mx2 = fmaxf(mx, ze);
        float sm2 = 0.f;
        for (int k = 0; k < NPIX; k++) sm2 += __expf(ztv[k] - mx2);
        sm2 += __expf(ze - mx2);
        out_beta[bt] = __expf(ze - mx2) / sm2;
    }
}

// ---------------------------------------------------------------------------
// c_spatial[bt,d] = sum_k alpha_t[bt,k] * V[b,k,d]   grid (64, 8) x 256
// ---------------------------------------------------------------------------
__global__ void cspatial_kernel(const float* __restrict__ V) {
    __shared__ float al[NPIX];
    const int bt = blockIdx.x, b = bt >> 3;
    if (threadIdx.x < NPIX) al[threadIdx.x] = g_alpha_t[bt * NPIX + threadIdx.x];
    __syncthreads();
    const int d = blockIdx.y * 256 + threadIdx.x;
    float s = 0.f;
    #pragma unroll 7
    for (int k = 0; k < NPIX; k++) s += al[k] * V[(b * NPIX + k) * CDIM + d];
    g_cspat[bt * CDIM + d] = s;
}

// ---------------------------------------------------------------------------
// gates: z=0 -> sgate, z=1 -> cgate. grid (16,4,2), 256 thr.
// ---------------------------------------------------------------------------
__global__ void gates_kernel(const float* __restrict__ hiddens,
                             const float* __restrict__ Wgvs,
                             const float* __restrict__ Wghs,
                             const float* __restrict__ Wgvc,
                             const float* __restrict__ Wghc) {
    __shared__ __align__(16) float As[16][64];
    const int op = blockIdx.z;
    const int n0 = blockIdx.x * 32, m0 = blockIdx.y * 16;
    const int col = n0 + (threadIdx.x & 31);
    const int rl  = (threadIdx.x >> 5) * 2;
    const int r0  = m0 + rl;
    float acc0 = 0.f, acc1 = 0.f;
    for (int phase = 0; phase < 2; ++phase) {
        const float* A = phase ? hiddens : g_s;
        const float* W = phase ? (op ? Wghc : Wghs) : (op ? Wgvc : Wgvs);
        for (int k0 = 0; k0 < 512; k0 += 64) {
            __syncthreads();
            for (int i = threadIdx.x; i < 1024; i += 256) {
                int r = m0 + (i >> 6), kk = i & 63;
                As[i >> 6][kk] = A[r * 512 + k0 + kk];
            }
            __syncthreads();
            #pragma unroll 8
            for (int kk = 0; kk < 64; kk++) {
                float w = W[(k0 + kk) * 512 + col];
                acc0 += As[rl][kk]     * w;
                acc1 += As[rl + 1][kk] * w;
            }
        }
    }
    float* out = op ? g_cgate : g_sgate;
    out[r0 * 512 + col]       = sigmoidf_(acc0);
    out[(r0 + 1) * 512 + col] = sigmoidf_(acc1);
}

// ---------------------------------------------------------------------------
// spat partial: grid (16,4,4), 256 thr
// ---------------------------------------------------------------------------
__global__ void spatpart_kernel(const float* __restrict__ Wspat) {
    __shared__ __align__(16) float As[16][64];
    const int zc = blockIdx.z, kb = zc * 512;
    const int n0 = blockIdx.x * 32, m0 = blockIdx.y * 16;
    const int col = n0 + (threadIdx.x & 31);
    const int rl  = (threadIdx.x >> 5) * 2;
    const int r0  = m0 + rl;
    float acc0 = 0.f, acc1 = 0.f;
    for (int k0 = 0; k0 < 512; k0 += 64) {
        __syncthreads();
        for (int i = threadIdx.x; i < 1024; i += 256) {
            int r = m0 + (i >> 6), kk = i & 63;
            As[i >> 6][kk] = g_cspat[r * CDIM + kb + k0 + kk];
        }
        __syncthreads();
        #pragma unroll 8
        for (int kk = 0; kk < 64; kk++) {
            float w = Wspat[(size_t)(kb + k0 + kk) * 512 + col];
            acc0 += As[rl][kk]     * w;
            acc1 += As[rl + 1][kk] * w;
        }
    }
    g_spart[(zc * BT + r0) * 512 + col]       = acc0;
    g_spart[(zc * BT + r0 + 1) * 512 + col]   = acc1;
}

// ---------------------------------------------------------------------------
// combine: g_chat = sgate*spat + cgate*(cchan@Wchan) + h.  64 x 512.
// ---------------------------------------------------------------------------
__global__ void combine_kernel(const float* __restrict__ hiddens,
                               const float* __restrict__ Wchan) {
    __shared__ float ch[NPIX];
    const int r = blockIdx.x, c = threadIdx.x;
    if (c < NPIX) {
        float v = 0.f;
        #pragma unroll
        for (int p = 0; p < DSPLIT; p++) v += g_cchanp[(p * BT + r) * NPIX + c];
        ch[c] = v * (1.0f / 2048.0f);
    }
    __syncthreads();
    float spat = g_spart[r * 512 + c]
               + g_spart[(BT + r) * 512 + c]
               + g_spart[(2 * BT + r) * 512 + c]
               + g_spart[(3 * BT + r) * 512 + c];
    float cb = 0.f;
    #pragma unroll 7
    for (int k = 0; k < NPIX; k++) cb += ch[k] * Wchan[k * 512 + c];
    g_chat[r * 512 + c] = g_sgate[r * 512 + c] * spat
                        + g_cgate[r * 512 + c] * cb
                        + hiddens[r * 512 + c];
}

// ---------------------------------------------------------------------------
// scores = chat @ Wmlp + bmlp.  grid 157, 256 thr, tile 64x64,
// thread = 4 rows x 4 cols (float4 weights; As reads warp-broadcast).
// ---------------------------------------------------------------------------
__global__ void scores_kernel(const float* __restrict__ Wmlp,
                              const float* __restrict__ bmlp,
                              float* __restrict__ out) {
    __shared__ __align__(16) float As[64][33];
    const int n0 = blockIdx.x * 64;
    const int rowg = threadIdx.x >> 4;       // 0..15 -> rows rowg*4..+3
    const int colg = threadIdx.x & 15;       // 0..15 -> cols n0+colg*4
    const int c0 = n0 + colg * 4;
    const bool okfull = (c0 + 3 < VOCAB);
    float acc[4][4];
    #pragma unroll
    for (int r = 0; r < 4; r++)
        #pragma unroll
        for (int j = 0; j < 4; j++) acc[r][j] = 0.f;
    for (int k0 = 0; k0 < 512; k0 += 32) {
        __syncthreads();
        for (int i = threadIdx.x; i < 2048; i += 256) {
            int r = i >> 5, kk = i & 31;
            As[r][kk] = g_chat[r * 512 + k0 + kk];
        }
        __syncthreads();
        #pragma unroll 4
        for (int kk = 0; kk < 32; kk++) {
            float4 w;
            if (okfull) {
                w = *reinterpret_cast<const float4*>(&Wmlp[(size_t)(k0 + kk) * VOCAB + c0]);
            } else {
                w.x = (c0     < VOCAB) ? Wmlp[(size_t)(k0 + kk) * VOCAB + c0]     : 0.f;
                w.y = (c0 + 1 < VOCAB) ? Wmlp[(size_t)(k0 + kk) * VOCAB + c0 + 1] : 0.f;
                w.z = (c0 + 2 < VOCAB) ? Wmlp[(size_t)(k0 + kk) * VOCAB + c0 + 2] : 0.f;
                w.w = (c0 + 3 < VOCAB) ? Wmlp[(size_t)(k0 + kk) * VOCAB + c0 + 3] : 0.f;
            }
            #pragma unroll
            for (int r = 0; r < 4; r++) {
                float a = As[rowg * 4 + r][kk];
                acc[r][0] += a * w.x;
                acc[r][1] += a * w.y;
                acc[r][2] += a * w.z;
                acc[r][3] += a * w.w;
            }
        }
    }
    #pragma unroll
    for (int j = 0; j < 4; j++) {
        int c = c0 + j;
        if (c < VOCAB) {
            float bb = bmlp[c];
            #pragma unroll
            for (int r = 0; r < 4; r++)
                out[(size_t)(rowg * 4 + r) * VOCAB + c] = acc[r][j] + bb;
        }
    }
}

// ---------------------------------------------------------------------------
extern "C" void kernel_launch(void* const* d_in, const int* in_sizes, int n_in,
                              void* d_out, int out_size) {
    (void)in_sizes; (void)n_in; (void)out_size;
    const float* x       = (const float*)d_in[0];
    const float* hiddens = (const float*)d_in[1];
    const float* cells   = (const float*)d_in[2];
    const float* V       = (const float*)d_in[3];
    const float* Wsx     = (const float*)d_in[4];
    const float* Wsh     = (const float*)d_in[5];
    const float* Wv      = (const float*)d_in[6];
    const float* Wg      = (const float*)d_in[7];
    const float* Ws      = (const float*)d_in[8];
    const float* Wh      = (const float*)d_in[9];
    const float* Wfeat   = (const float*)d_in[10];
    const float* Wcxt    = (const float*)d_in[11];
    const float* Wg2     = (const float*)d_in[12];
    const float* Wspat   = (const float*)d_in[13];
    const float* Wchan   = (const float*)d_in[14];
    const float* Wgvs    = (const float*)d_in[15];
    const float* Wgvc    = (const float*)d_in[16];
    const float* Wghs    = (const float*)d_in[17];
    const float* Wghc    = (const float*)d_in[18];
    const float* Wmlp    = (const float*)d_in[19];
    const float* bmlp    = (const float*)d_in[20];

    float* out        = (float*)d_out;
    float* out_scores = out;
    float* out_alpha  = out + BT * VOCAB;
    float* out_beta   = out + BT * VOCAB + BT * NPIX;

    pre_kernel<<<dim3(16, 4, 2), 256>>>(x, hiddens, cells, Wsx, Wsh, Wg2);
    cxt_kernel<<<dim3(64, 4), 128>>>(V, Wfeat, Wcxt);
    softmax2048_kernel<<<64, 256>>>();
    gates_kernel<<<dim3(16, 4, 2), 256>>>(hiddens, Wgvs, Wghs, Wgvc, Wghc);
    wfwv_kernel<<<dim3(64, DSPLIT), 192>>>(V, Wv);
    zt_kernel<<<64, 64>>>(hiddens, Wg, Ws, Wh, out_alpha, out_beta);
    cspatial_kernel<<<dim3(64, 8), 256>>>(V);
    spatpart_kernel<<<dim3(16, 4, 4), 256>>>(Wspat);
    combine_kernel<<<64, 512>>>(hiddens, Wchan);
    scores_kernel<<<157, 256>>>(Wmlp, bmlp, out_scores);
}

// round 8
// speedup vs baseline: 1.7379x; 1.6351x over previous
#include <cuda_runtime.h>
#include <math.h>

#define BT    64
#define NPIX  49
#define CDIM  2048
#define VOCAB 10000
#define DSPLIT 8

// ---------------- scratch ----------------
__device__ float g_prep[4*2*BT*512];     // [ks][op][64][512] op0: s-preact, op1: g2
__device__ float g_alpha0[BT*CDIM];
__device__ float g_Mpart[DSPLIT*BT*NPIX*NPIX];
__device__ float g_cchanp[DSPLIT*BT*NPIX];
__device__ float g_alpha_t[BT*NPIX];
__device__ float g_cspat[BT*CDIM];
__device__ float g_gatep[4*2*BT*512];    // [ks][op][64][512] op0: sgate-pre, op1: cgate-pre
__device__ float g_spart[4*BT*512];
__device__ float g_chat[BT*512];
__device__ float g_scorep[4*BT*VOCAB];   // score partials

__device__ __forceinline__ float tanh_fast(float x) {
    float y;
    asm("tanh.approx.f32 %0, %1;" : "=f"(y) : "f"(x));
    return y;
}
__device__ __forceinline__ float sigmoidf_(float x) {
    return 1.0f / (1.0f + __expf(-x));
}
// reconstruct s[r, c] from 4 pre-activation partials
__device__ __forceinline__ float s_val(int r, int c, const float* __restrict__ cells) {
    float p = g_prep[((0*2+0)*BT + r)*512 + c]
            + g_prep[((1*2+0)*BT + r)*512 + c]
            + g_prep[((2*2+0)*BT + r)*512 + c]
            + g_prep[((3*2+0)*BT + r)*512 + c];
    return sigmoidf_(p) * tanh_fast(cells[r*512 + c]);
}

// ---------------------------------------------------------------------------
// pre: op0 partial of x@Wsx + hprev@Wsh ; op1 partial of h@Wg2.
// grid (16 colTiles, 4 rowTiles x 4 ksplit, 2 ops), 256 thr.
// ---------------------------------------------------------------------------
__global__ void pre_kernel(const float* __restrict__ x,
                           const float* __restrict__ hiddens,
                           const float* __restrict__ Wsx,
                           const float* __restrict__ Wsh,
                           const float* __restrict__ Wg2) {
    __shared__ __align__(16) float As[16][64];
    const int op = blockIdx.z;
    const int ks = blockIdx.y >> 2;
    const int m0 = (blockIdx.y & 3) * 16;
    const int n0 = blockIdx.x * 32;
    const int kbase = ks * 128;
    const int col = n0 + (threadIdx.x & 31);
    const int rl  = (threadIdx.x >> 5) * 2;
    const int r0  = m0 + rl;
    float acc0 = 0.f, acc1 = 0.f;
    const int nph = (op == 0) ? 2 : 1;
    for (int phase = 0; phase < nph; ++phase) {
        const float* W = (op == 0) ? (phase ? Wsh : Wsx) : Wg2;
        for (int k0 = kbase; k0 < kbase + 128; k0 += 64) {
            __syncthreads();
            for (int i = threadIdx.x; i < 1024; i += 256) {
                int r = m0 + (i >> 6), kk = i & 63;
                float v;
                if (op == 0 && phase == 1) v = (r & 7) ? hiddens[(r - 1) * 512 + k0 + kk] : 0.f;
                else if (op == 0)          v = x[r * 512 + k0 + kk];
                else                       v = hiddens[r * 512 + k0 + kk];
                As[i >> 6][kk] = v;
            }
            __syncthreads();
            #pragma unroll 8
            for (int kk = 0; kk < 64; kk++) {
                float w = W[(k0 + kk) * 512 + col];
                acc0 += As[rl][kk]     * w;
                acc1 += As[rl + 1][kk] * w;
            }
        }
    }
    g_prep[((ks*2 + op)*BT + r0)*512 + col]       = acc0;
    g_prep[((ks*2 + op)*BT + r0 + 1)*512 + col]   = acc1;
}

// ---------------------------------------------------------------------------
// cxt with fused featmean; g2 summed from partials. grid (64, 4), 128 thr.
// ---------------------------------------------------------------------------
__global__ void cxt_kernel(const float* __restrict__ V,
                           const float* __restrict__ Wfeat,
                           const float* __restrict__ Wcxt) {
    __shared__ __align__(16) float wf[512];
    __shared__ __align__(16) float wc[512];
    __shared__ __align__(16) float gr[512];
    const int bt = blockIdx.x, b = bt >> 3;
    const int t = threadIdx.x;
    for (int i = t; i < 512; i += 128) {
        wf[i] = Wfeat[i];
        wc[i] = Wcxt[i];
        gr[i] = g_prep[((0*2+1)*BT + bt)*512 + i]
              + g_prep[((1*2+1)*BT + bt)*512 + i]
              + g_prep[((2*2+1)*BT + bt)*512 + i]
              + g_prep[((3*2+1)*BT + bt)*512 + i];
    }
    const int d0 = blockIdx.y * 512 + t;
    float a[4];
    #pragma unroll
    for (int q = 0; q < 4; q++) {
        int d = d0 + 128 * q;
        float s = 0.f;
        #pragma unroll 7
        for (int k = 0; k < NPIX; k++) s += V[(b * NPIX + k) * CDIM + d];
        a[q] = s * (1.0f / 49.0f);
    }
    __syncthreads();
    float c0 = 0.f, c1 = 0.f, c2 = 0.f, c3 = 0.f;
    #pragma unroll 4
    for (int j = 0; j < 512; j++) {
        float wfj = wf[j], grj = gr[j], wcj = wc[j];
        c0 += tanh_fast(fmaf(a[0], wfj, grj)) * wcj;
        c1 += tanh_fast(fmaf(a[1], wfj, grj)) * wcj;
        c2 += tanh_fast(fmaf(a[2], wfj, grj)) * wcj;
        c3 += tanh_fast(fmaf(a[3], wfj, grj)) * wcj;
    }
    g_alpha0[bt * CDIM + d0]       = c0;
    g_alpha0[bt * CDIM + d0 + 128] = c1;
    g_alpha0[bt * CDIM + d0 + 256] = c2;
    g_alpha0[bt * CDIM + d0 + 384] = c3;
}

// ---------------------------------------------------------------------------
// softmax over 2048 per bt (in place)
// ---------------------------------------------------------------------------
__global__ void softmax2048_kernel() {
    __shared__ float red[256];
    const int bt = blockIdx.x, t = threadIdx.x;
    float* p = g_alpha0 + bt * CDIM;
    float mx = -1e30f;
    for (int i = t; i < CDIM; i += 256) mx = fmaxf(mx, p[i]);
    red[t] = mx; __syncthreads();
    for (int s = 128; s > 0; s >>= 1) { if (t < s) red[t] = fmaxf(red[t], red[t + s]); __syncthreads(); }
    mx = red[0]; __syncthreads();
    float sm = 0.f;
    for (int i = t; i < CDIM; i += 256) { float e = __expf(p[i] - mx); p[i] = e; sm += e; }
    red[t] = sm; __syncthreads();
    for (int s = 128; s > 0; s >>= 1) { if (t < s) red[t] += red[t + s]; __syncthreads(); }
    float inv = 1.0f / red[0];
    for (int i = t; i < CDIM; i += 256) p[i] *= inv;
}

// ---------------------------------------------------------------------------
// gates partials: op0 -> s@Wgvs + h@Wghs, op1 -> s@Wgvc + h@Wghc (k-range 128).
// grid (16 colTiles, 4 rowTiles x 4 ksplit, 2 ops), 256 thr.
// ---------------------------------------------------------------------------
__global__ void gates_kernel(const float* __restrict__ hiddens,
                             const float* __restrict__ cells,
                             const float* __restrict__ Wgvs,
                             const float* __restrict__ Wghs,
                             const float* __restrict__ Wgvc,
                             const float* __restrict__ Wghc) {
    __shared__ __align__(16) float As[16][64];
    const int op = blockIdx.z;
    const int ks = blockIdx.y >> 2;
    const int m0 = (blockIdx.y & 3) * 16;
    const int n0 = blockIdx.x * 32;
    const int kbase = ks * 128;
    const int col = n0 + (threadIdx.x & 31);
    const int rl  = (threadIdx.x >> 5) * 2;
    const int r0  = m0 + rl;
    float acc0 = 0.f, acc1 = 0.f;
    for (int phase = 0; phase < 2; ++phase) {
        const float* W = phase ? (op ? Wghc : Wghs) : (op ? Wgvc : Wgvs);
        for (int k0 = kbase; k0 < kbase + 128; k0 += 64) {
            __syncthreads();
            for (int i = threadIdx.x; i < 1024; i += 256) {
                int r = m0 + (i >> 6), kk = i & 63;
                As[i >> 6][kk] = phase ? hiddens[r * 512 + k0 + kk]
                                       : s_val(r, k0 + kk, cells);
            }
            __syncthreads();
            #pragma unroll 8
            for (int kk = 0; kk < 64; kk++) {
                float w = W[(k0 + kk) * 512 + col];
                acc0 += As[rl][kk]     * w;
                acc1 += As[rl + 1][kk] * w;
            }
        }
    }
    g_gatep[((ks*2 + op)*BT + r0)*512 + col]     = acc0;
    g_gatep[((ks*2 + op)*BT + r0 + 1)*512 + col] = acc1;
}

// ---------------------------------------------------------------------------
// wfwv: M partials + cchan partials. grid (64 bt, 8 dp), 192 thr, K=256/blk.
// ---------------------------------------------------------------------------
__global__ void wfwv_kernel(const float* __restrict__ V,
                            const float* __restrict__ Wv) {
    __shared__ __align__(16) float Wvs[64][52];
    __shared__ __align__(16) float aV[49][65];
    __shared__ __align__(16) float as_[256];
    const int bt = blockIdx.x, b = bt >> 3;
    const int dp = blockIdx.y, d0 = dp * 256;
    const int t = threadIdx.x;
    for (int i = t; i < 256; i += 192) as_[i] = g_alpha0[bt * CDIM + d0 + i];
    if (t < 64) { Wvs[t][49] = 0.f; Wvs[t][50] = 0.f; Wvs[t][51] = 0.f; }
    const int tk = t / 13, tk2 = t % 13;
    const bool active = (t < 169);
    int ki[4];
    #pragma unroll
    for (int i = 0; i < 4; i++) ki[i] = min(tk * 4 + i, 48);
    float acc[4][4];
    #pragma unroll
    for (int i = 0; i < 4; i++)
        #pragma unroll
        for (int j = 0; j < 4; j++) acc[i][j] = 0.f;
    float chs0 = 0.f, chs1 = 0.f, chs2 = 0.f;
    const int crow = t - 169;
    for (int c = 0; c < 4; c++) {
        __syncthreads();
        for (int i = t; i < 49 * 64; i += 192) {
            int r = i >> 6, dd = i & 63;
            aV[r][dd] = V[(b * NPIX + r) * CDIM + d0 + c * 64 + dd] * as_[c * 64 + dd];
        }
        for (int i = t; i < 64 * 49; i += 192) {
            Wvs[i / 49][i % 49] = Wv[(size_t)(d0 + c * 64) * NPIX + i];
        }
        __syncthreads();
        if (active) {
            #pragma unroll 4
            for (int dd = 0; dd < 64; dd++) {
                const float4 wv = *reinterpret_cast<const float4*>(&Wvs[dd][tk2 * 4]);
                float av0 = aV[ki[0]][dd], av1 = aV[ki[1]][dd];
                float av2 = aV[ki[2]][dd], av3 = aV[ki[3]][dd];
                acc[0][0] += av0 * wv.x; acc[0][1] += av0 * wv.y; acc[0][2] += av0 * wv.z; acc[0][3] += av0 * wv.w;
                acc[1][0] += av1 * wv.x; acc[1][1] += av1 * wv.y; acc[1][2] += av1 * wv.z; acc[1][3] += av1 * wv.w;
                acc[2][0] += av2 * wv.x; acc[2][1] += av2 * wv.y; acc[2][2] += av2 * wv.z; acc[2][3] += av2 * wv.w;
                acc[3][0] += av3 * wv.x; acc[3][1] += av3 * wv.y; acc[3][2] += av3 * wv.z; acc[3][3] += av3 * wv.w;
            }
        } else {
            float s0 = 0.f, s1 = 0.f, s2 = 0.f;
            #pragma unroll 8
            for (int dd = 0; dd < 64; dd++) {
                s0 += aV[crow][dd];
                if (crow + 23 < 49) s1 += aV[crow + 23][dd];
                if (crow + 46 < 49) s2 += aV[crow + 46][dd];
            }
            chs0 += s0; chs1 += s1; chs2 += s2;
        }
    }
    if (active) {
        #pragma unroll
        for (int i = 0; i < 4; i++) {
            int k = tk * 4 + i;
            if (k >= NPIX) continue;
            #pragma unroll
            for (int j = 0; j < 4; j++) {
                int k2 = tk2 * 4 + j;
                if (k2 < NPIX)
                    g_Mpart[(((size_t)dp * BT + bt) * NPIX + k) * NPIX + k2] = acc[i][j];
            }
        }
    } else {
        g_cchanp[(dp * BT + bt) * NPIX + crow] = chs0;
        if (crow + 23 < 49) g_cchanp[(dp * BT + bt) * NPIX + crow + 23] = chs1;
        if (crow + 46 < 49) g_cchanp[(dp * BT + bt) * NPIX + crow + 46] = chs2;
    }
}

// ---------------------------------------------------------------------------
// zt: fused gcs + z_t + softmaxes. grid 64 blocks x 64 thr.
// ---------------------------------------------------------------------------
__global__ void zt_kernel(const float* __restrict__ hiddens,
                          const float* __restrict__ cells,
                          const float* __restrict__ Wg,
                          const float* __restrict__ Ws,
                          const float* __restrict__ Wh,
                          float* __restrict__ out_alpha,
                          float* __restrict__ out_beta) {
    __shared__ float h_sm[512], s_sm[512];
    __shared__ float Msum[NPIX * NPIX];
    __shared__ float gg[NPIX], css[NPIX], wh[NPIX], ztv[NPIX];
    const int bt = blockIdx.x, t = threadIdx.x;
    for (int i = t; i < 512; i += 64) {
        h_sm[i] = hiddens[bt * 512 + i];
        s_sm[i] = s_val(bt, i, cells);
    }
    if (t < NPIX) wh[t] = Wh[t];
    {
        const float* p0 = g_Mpart + (size_t)bt * NPIX * NPIX;
        const size_t stride = (size_t)BT * NPIX * NPIX;
        for (int i = t; i < NPIX * NPIX; i += 64) {
            float v = 0.f;
            #pragma unroll
            for (int p = 0; p < DSPLIT; p++) v += p0[p * stride + i];
            Msum[i] = v;
        }
    }
    __syncthreads();
    if (t < NPIX) {
        float ggv = 0.f, ssv = 0.f;
        #pragma unroll 8
        for (int k = 0; k < 512; k++) {
            ggv += h_sm[k] * Wg[k * NPIX + t];
            ssv += s_sm[k] * Ws[k * NPIX + t];
        }
        gg[t] = ggv;
        css[t] = ssv + ggv;
    }
    __syncthreads();
    if (t < NPIX) {
        float z = 0.f;
        #pragma unroll 7
        for (int k2 = 0; k2 < NPIX; k2++)
            z += tanh_fast(tanh_fast(Msum[t * NPIX + k2] + gg[k2])) * wh[k2];
        ztv[t] = z;
    }
    __syncthreads();
    if (t == 0) {
        float ze = 0.f;
        for (int k = 0; k < NPIX; k++) ze += tanh_fast(css[k]) * wh[k];
        float mx = -1e30f;
        for (int k = 0; k < NPIX; k++) mx = fmaxf(mx, ztv[k]);
        float sm = 0.f;
        for (int k = 0; k < NPIX; k++) sm += __expf(ztv[k] - mx);
        float inv = 1.0f / sm;
        for (int k = 0; k < NPIX; k++) {
            float a = __expf(ztv[k] - mx) * inv;
            g_alpha_t[bt * NPIX + k] = a;
            out_alpha[bt * NPIX + k] = a;
        }
        float mx2 = fmaxf(mx, ze);
        float sm2 = 0.f;
        for (int k = 0; k < NPIX; k++) sm2 += __expf(ztv[k] - mx2);
        sm2 += __expf(ze - mx2);
        out_beta[bt] = __expf(ze - mx2) / sm2;
    }
}

// ---------------------------------------------------------------------------
// c_spatial[bt,d] = sum_k alpha_t[bt,k] * V[b,k,d]   grid (64, 8) x 256
// ---------------------------------------------------------------------------
__global__ void cspatial_kernel(const float* __restrict__ V) {
    __shared__ float al[NPIX];
    const int bt = blockIdx.x, b = bt >> 3;
    if (threadIdx.x < NPIX) al[threadIdx.x] = g_alpha_t[bt * NPIX + threadIdx.x];
    __syncthreads();
    const int d = blockIdx.y * 256 + threadIdx.x;
    float s = 0.f;
    #pragma unroll 7
    for (int k = 0; k < NPIX; k++) s += al[k] * V[(b * NPIX + k) * CDIM + d];
    g_cspat[bt * CDIM + d] = s;
}

// ---------------------------------------------------------------------------
// spat partial: grid (16,4,4), 256 thr  (ksplit over CDIM chunks of 512)
// ---------------------------------------------------------------------------
__global__ void spatpart_kernel(const float* __restrict__ Wspat) {
    __shared__ __align__(16) float As[16][64];
    const int zc = blockIdx.z, kb = zc * 512;
    const int n0 = blockIdx.x * 32, m0 = blockIdx.y * 16;
    const int col = n0 + (threadIdx.x & 31);
    const int rl  = (threadIdx.x >> 5) * 2;
    const int r0  = m0 + rl;
    float acc0 = 0.f, acc1 = 0.f;
    for (int k0 = 0; k0 < 512; k0 += 64) {
        __syncthreads();
        for (int i = threadIdx.x; i < 1024; i += 256) {
            int r = m0 + (i >> 6), kk = i & 63;
            As[i >> 6][kk] = g_cspat[r * CDIM + kb + k0 + kk];
        }
        __syncthreads();
        #pragma unroll 8
        for (int kk = 0; kk < 64; kk++) {
            float w = Wspat[(size_t)(kb + k0 + kk) * 512 + col];
            acc0 += As[rl][kk]     * w;
            acc1 += As[rl + 1][kk] * w;
        }
    }
    g_spart[(zc * BT + r0) * 512 + col]       = acc0;
    g_spart[(zc * BT + r0 + 1) * 512 + col]   = acc1;
}

// ---------------------------------------------------------------------------
// combine: chat = sig(gatep0)*spat + sig(gatep1)*(cchan@Wchan) + h.  64 x 512.
// ---------------------------------------------------------------------------
__global__ void combine_kernel(const float* __restrict__ hiddens,
                               const float* __restrict__ Wchan) {
    __shared__ float ch[NPIX];
    const int r = blockIdx.x, c = threadIdx.x;
    if (c < NPIX) {
        float v = 0.f;
        #pragma unroll
        for (int p = 0; p < DSPLIT; p++) v += g_cchanp[(p * BT + r) * NPIX + c];
        ch[c] = v * (1.0f / 2048.0f);
    }
    __syncthreads();
    float spat = g_spart[r * 512 + c]
               + g_spart[(BT + r) * 512 + c]
               + g_spart[(2 * BT + r) * 512 + c]
               + g_spart[(3 * BT + r) * 512 + c];
    float sg = 0.f, cg = 0.f;
    #pragma unroll
    for (int ks = 0; ks < 4; ks++) {
        sg += g_gatep[((ks*2 + 0)*BT + r)*512 + c];
        cg += g_gatep[((ks*2 + 1)*BT + r)*512 + c];
    }
    float cb = 0.f;
    #pragma unroll 7
    for (int k = 0; k < NPIX; k++) cb += ch[k] * Wchan[k * 512 + c];
    g_chat[r * 512 + c] = sigmoidf_(sg) * spat
                        + sigmoidf_(cg) * cb
                        + hiddens[r * 512 + c];
}

// ---------------------------------------------------------------------------
// scores partials: grid (157, 4 ksplit), 256 thr, tile 64x64, k-range 128.
// ---------------------------------------------------------------------------
__global__ void scores_kernel(const float* __restrict__ Wmlp) {
    __shared__ __align__(16) float As[64][33];
    const int n0 = blockIdx.x * 64;
    const int ks = blockIdx.y;
    const int kbase = ks * 128;
    const int rowg = threadIdx.x >> 4;
    const int colg = threadIdx.x & 15;
    const int c0 = n0 + colg * 4;
    const bool okfull = (c0 + 3 < VOCAB);
    float* outp = g_scorep + (size_t)ks * BT * VOCAB;
    float acc[4][4];
    #pragma unroll
    for (int r = 0; r < 4; r++)
        #pragma unroll
        for (int j = 0; j < 4; j++) acc[r][j] = 0.f;
    for (int k0 = kbase; k0 < kbase + 128; k0 += 32) {
        __syncthreads();
        for (int i = threadIdx.x; i < 2048; i += 256) {
            int r = i >> 5, kk = i & 31;
            As[r][kk] = g_chat[r * 512 + k0 + kk];
        }
        __syncthreads();
        #pragma unroll 4
        for (int kk = 0; kk < 32; kk++) {
            float4 w;
            if (okfull) {
                w = *reinterpret_cast<const float4*>(&Wmlp[(size_t)(k0 + kk) * VOCAB + c0]);
            } else {
                w.x = (c0     < VOCAB) ? Wmlp[(size_t)(k0 + kk) * VOCAB + c0]     : 0.f;
                w.y = (c0 + 1 < VOCAB) ? Wmlp[(size_t)(k0 + kk) * VOCAB + c0 + 1] : 0.f;
                w.z = (c0 + 2 < VOCAB) ? Wmlp[(size_t)(k0 + kk) * VOCAB + c0 + 2] : 0.f;
                w.w = (c0 + 3 < VOCAB) ? Wmlp[(size_t)(k0 + kk) * VOCAB + c0 + 3] : 0.f;
            }
            #pragma unroll
            for (int r = 0; r < 4; r++) {
                float a = As[rowg * 4 + r][kk];
                acc[r][0] += a * w.x;
                acc[r][1] += a * w.y;
                acc[r][2] += a * w.z;
                acc[r][3] += a * w.w;
            }
        }
    }
    #pragma unroll
    for (int j = 0; j < 4; j++) {
        int c = c0 + j;
        if (c < VOCAB) {
            #pragma unroll
            for (int r = 0; r < 4; r++)
                outp[(size_t)(rowg * 4 + r) * VOCAB + c] = acc[r][j];
        }
    }
}

// ---------------------------------------------------------------------------
// reduce scores: out = sum of 4 partials + bias.  625 blocks x 256, float4.
// ---------------------------------------------------------------------------
__global__ void reduce_scores_kernel(const float* __restrict__ bmlp,
                                     float* __restrict__ out) {
    const int idx = (blockIdx.x * 256 + threadIdx.x) * 4;   // < 640000
    const float4 p0 = *reinterpret_cast<const float4*>(&g_scorep[idx]);
    const float4 p1 = *reinterpret_cast<const float4*>(&g_scorep[BT*VOCAB + idx]);
    const float4 p2 = *reinterpret_cast<const float4*>(&g_scorep[2*BT*VOCAB + idx]);
    const float4 p3 = *reinterpret_cast<const float4*>(&g_scorep[3*BT*VOCAB + idx]);
    const int c = idx % VOCAB;
    const float4 b = *reinterpret_cast<const float4*>(&bmlp[c]);
    float4 r;
    r.x = p0.x + p1.x + p2.x + p3.x + b.x;
    r.y = p0.y + p1.y + p2.y + p3.y + b.y;
    r.z = p0.z + p1.z + p2.z + p3.z + b.z;
    r.w = p0.w + p1.w + p2.w + p3.w + b.w;
    *reinterpret_cast<float4*>(&out[idx]) = r;
}

// ---------------------------------------------------------------------------
extern "C" void kernel_launch(void* const* d_in, const int* in_sizes, int n_in,
                              void* d_out, int out_size) {
    (void)in_sizes; (void)n_in; (void)out_size;
    const float* x       = (const float*)d_in[0];
    const float* hiddens = (const float*)d_in[1];
    const float* cells   = (const float*)d_in[2];
    const float* V       = (const float*)d_in[3];
    const float* Wsx     = (const float*)d_in[4];
    const float* Wsh     = (const float*)d_in[5];
    const float* Wv      = (const float*)d_in[6];
    const float* Wg      = (const float*)d_in[7];
    const float* Ws      = (const float*)d_in[8];
    const float* Wh      = (const float*)d_in[9];
    const float* Wfeat   = (const float*)d_in[10];
    const float* Wcxt    = (const float*)d_in[11];
    const float* Wg2     = (const float*)d_in[12];
    const float* Wspat   = (const float*)d_in[13];
    const float* Wchan   = (const float*)d_in[14];
    const float* Wgvs    = (const float*)d_in[15];
    const float* Wgvc    = (const float*)d_in[16];
    const float* Wghs    = (const float*)d_in[17];
    const float* Wghc    = (const float*)d_in[18];
    const float* Wmlp    = (const float*)d_in[19];
    const float* bmlp    = (const float*)d_in[20];

    float* out        = (float*)d_out;
    float* out_scores = out;
    float* out_alpha  = out + BT * VOCAB;
    float* out_beta   = out + BT * VOCAB + BT * NPIX;

    pre_kernel<<<dim3(16, 16, 2), 256>>>(x, hiddens, Wsx, Wsh, Wg2);
    cxt_kernel<<<dim3(64, 4), 128>>>(V, Wfeat, Wcxt);
    softmax2048_kernel<<<64, 256>>>();
    gates_kernel<<<dim3(16, 16, 2), 256>>>(hiddens, cells, Wgvs, Wghs, Wgvc, Wghc);
    wfwv_kernel<<<dim3(64, DSPLIT), 192>>>(V, Wv);
    zt_kernel<<<64, 64>>>(hiddens, cells, Wg, Ws, Wh, out_alpha, out_beta);
    cspatial_kernel<<<dim3(64, 8), 256>>>(V);
    spatpart_kernel<<<dim3(16, 4, 4), 256>>>(Wspat);
    combine_kernel<<<64, 512>>>(hiddens, Wchan);
    scores_kernel<<<dim3(157, 4), 256>>>(Wmlp);
    reduce_scores_kernel<<<625, 256>>>(bmlp, out_scores);
}